// round 10
// baseline (speedup 1.0000x reference)
#include <cuda_runtime.h>
#include <cuda_fp16.h>
#include <math.h>

#define NN 50000
#define NE 800000
#define FD 256
#define HEADS 4
#define CH 64

// ---- scratch (static device globals: no runtime allocation) ----
__device__ __half g_h[(size_t)NN * FD];    // GEMM output (fp16 gather payload)
__device__ float  g_y[(size_t)NN * FD];    // layer-1 output (GEMM2 input)
__device__ float  g_asrc[NN * HEADS];
__device__ float  g_adst[NN * HEADS];
__device__ int    g_cnt[NN];
__device__ int    g_off[NN + 1];
__device__ int    g_col[NE];               // CSR: src per position

__device__ __forceinline__ float lrelu(float x) { return fmaxf(x, 0.2f * x); }

__device__ __forceinline__ unsigned f2tf(float f) {
    unsigned u;
    asm("cvt.rna.tf32.f32 %0, %1;" : "=r"(u) : "f"(f));
    return u;
}

__device__ __forceinline__ void mma_tf32(float* c, const unsigned* a, const unsigned* b) {
    asm volatile(
        "mma.sync.aligned.m16n8k8.row.col.f32.tf32.tf32.f32 "
        "{%0,%1,%2,%3},{%4,%5,%6,%7},{%8,%9},{%0,%1,%2,%3};"
        : "+f"(c[0]), "+f"(c[1]), "+f"(c[2]), "+f"(c[3])
        : "r"(a[0]), "r"(a[1]), "r"(a[2]), "r"(a[3]), "r"(b[0]), "r"(b[1]));
}

// ---------------- CSR build ----------------
__global__ void k_zero_cnt() {
    int i = blockIdx.x * blockDim.x + threadIdx.x;
    if (i < NN) g_cnt[i] = 0;
}

__global__ void k_hist(const int* __restrict__ dst) {
    int e = blockIdx.x * blockDim.x + threadIdx.x;
    if (e < NE) atomicAdd(&g_cnt[dst[e]], 1);
}

// single-block shuffle scan: 1024 threads x 49 contiguous counts each.
__global__ void k_scan() {
    const int T = 1024, PER = (NN + T - 1) / T;   // 49
    __shared__ int wsum[32];
    const int t = threadIdx.x, lane = t & 31, wid = t >> 5;
    const int base = t * PER;

    int sum = 0;
    for (int i = 0; i < PER; i++) {
        int idx = base + i;
        if (idx < NN) sum += g_cnt[idx];
    }
    int v = sum;
#pragma unroll
    for (int o = 1; o < 32; o <<= 1) {
        int n = __shfl_up_sync(0xffffffffu, v, o);
        if (lane >= o) v += n;
    }
    if (lane == 31) wsum[wid] = v;
    __syncthreads();
    if (wid == 0) {
        int wv = wsum[lane];
#pragma unroll
        for (int o = 1; o < 32; o <<= 1) {
            int n = __shfl_up_sync(0xffffffffu, wv, o);
            if (lane >= o) wv += n;
        }
        wsum[lane] = wv;
    }
    __syncthreads();
    int run = v - sum + (wid > 0 ? wsum[wid - 1] : 0);
    for (int i = 0; i < PER; i++) {
        int idx = base + i;
        if (idx < NN) {
            int c = g_cnt[idx];
            g_off[idx] = run;
            run += c;
            g_cnt[idx] = 0;
        }
    }
    if (t == 0) g_off[NN] = wsum[31];
}

__global__ void k_scatter(const int* __restrict__ src, const int* __restrict__ dst) {
    int e = blockIdx.x * blockDim.x + threadIdx.x;
    if (e < NE) {
        int d = dst[e];
        int pos = g_off[d] + atomicAdd(&g_cnt[d], 1);
        g_col[pos] = src[e];
    }
}

// ---------------- tf32 tensor-core GEMM + fused attention-logit epilogue ----
// R6 geometry: block 64(M) x 256(N), BK=16, 8 warps = 2 wm x 4 wn; warp 32x64.
// A-PREFETCH DEPTH 2: two float4 A loads in flight per thread so the ~600cyc
// A-stream (L2/DRAM) latency is covered by ~2 chunks of compute. LDGs issued
// BEFORE the barrier. A fragment-major in smem (one LDS.128 = one m16k8
// fragment); B depth-1 (W is L1-hot). One __syncthreads per chunk.
__global__ void __launch_bounds__(256) k_gemm_att(
    const float* __restrict__ Ain,          // nullptr -> use g_y
    const float* __restrict__ W,
    const float* __restrict__ att_s,
    const float* __restrict__ att_d)
{
    const float* A = Ain ? Ain : g_y;
    __shared__ unsigned sAf[2][1024];       // fragment-major A (4KB/stage)
    __shared__ unsigned sB[2][16][264];     // [k][n] stride 264 (conflict-free)

    const int t    = threadIdx.x;
    const int lane = t & 31;
    const int wid  = t >> 5;
    const int gid  = lane >> 2, tig = lane & 3;
    const int wm   = wid & 1,   wn  = wid >> 1;   // rows wm*32, cols wn*64
    const int row0 = blockIdx.x * 64;

    float acc[2][8][4] = {};

    // ---- staging indices ----
    const int ar = t >> 2, acb = (t & 3) * 4;     // A: row ar, cols acb..acb+3
    const int br = t >> 4, bc = (t & 15) * 4;     // B: row br, 4x 64-strided float4
    const bool arow_ok = (row0 + ar) < NN;
    const float* aptr = A + (size_t)(row0 + ar) * FD + acb;
    const float* bptr = W + (size_t)br * FD + bc;

    // A store word addresses (loop-invariant): fragment-major layout
    int a_st[4];
    {
        const int wm_s = ar >> 5, tm_s = (ar >> 4) & 1;
        const int rh_s = (ar >> 3) & 1, gid_s = ar & 7;
#pragma unroll
        for (int j = 0; j < 4; j++) {
            const int k = acb + j;
            const int kkb = k >> 3, tg = k & 3, kh = (k >> 2) & 1;
            a_st[j] = (kkb * 128 + wm_s * 64 + tm_s * 32 + gid_s * 4 + tg) * 4
                      + rh_s + 2 * kh;
        }
    }
    const int a_rd0 = (wm * 64 + gid * 4 + tig) * 4;
    const int b_rd  = tig * 264 + wn * 64 + gid;

    // depth-2 A prefetch registers + depth-1 B
    float4 aval[2];
    aval[0] = make_float4(0.f, 0.f, 0.f, 0.f);
    aval[1] = aval[0];
    if (arow_ok) {
        aval[0] = *(const float4*)aptr;           // chunk 0
        aval[1] = *(const float4*)(aptr + 16);    // chunk 1
    }
    float4 bval[4];
#pragma unroll
    for (int sub = 0; sub < 4; sub++)
        bval[sub] = *(const float4*)(bptr + sub * 64);

    int st = 0;
    for (int k0 = 0; k0 < FD; k0 += 16) {
        const int pi = (k0 >> 4) & 1;
        sAf[st][a_st[0]] = f2tf(aval[pi].x);
        sAf[st][a_st[1]] = f2tf(aval[pi].y);
        sAf[st][a_st[2]] = f2tf(aval[pi].z);
        sAf[st][a_st[3]] = f2tf(aval[pi].w);
#pragma unroll
        for (int sub = 0; sub < 4; sub++)
            *(uint4*)&sB[st][br][bc + sub * 64] =
                make_uint4(f2tf(bval[sub].x), f2tf(bval[sub].y),
                           f2tf(bval[sub].z), f2tf(bval[sub].w));
        // issue next LDGs BEFORE the barrier (regs just freed by the STS)
        if (k0 + 32 < FD && arow_ok)
            aval[pi] = *(const float4*)(aptr + k0 + 32);      // depth 2
        if (k0 + 16 < FD) {
#pragma unroll
            for (int sub = 0; sub < 4; sub++)
                bval[sub] = *(const float4*)(bptr + (size_t)(k0 + 16) * FD + sub * 64);
        }
        __syncthreads();

        const unsigned* sa = sAf[st];
        const unsigned* sb = &sB[st][0][0] + b_rd;
#pragma unroll
        for (int kkb = 0; kkb < 2; kkb++) {
            uint4 af0 = *(const uint4*)(sa + kkb * 512 + a_rd0);        // tm=0
            uint4 af1 = *(const uint4*)(sa + kkb * 512 + a_rd0 + 128);  // tm=1
            const unsigned* b0 = sb + kkb * (8 * 264);
            unsigned bf[8][2];
#pragma unroll
            for (int tn = 0; tn < 8; tn++) {
                bf[tn][0] = b0[tn * 8];
                bf[tn][1] = b0[4 * 264 + tn * 8];
            }
#pragma unroll
            for (int tn = 0; tn < 8; tn++) {
                mma_tf32(acc[0][tn], (const unsigned*)&af0, bf[tn]);
                mma_tf32(acc[1][tn], (const unsigned*)&af1, bf[tn]);
            }
        }
        st ^= 1;
    }

    // ---- epilogue: store h (fp16), fused per-head attention dots ----
    const int head = wn;
#pragma unroll
    for (int tm = 0; tm < 2; tm++) {
#pragma unroll
        for (int rh = 0; rh < 2; rh++) {
            const int r = row0 + wm * 32 + tm * 16 + rh * 8 + gid;
            const bool rok = r < NN;
            float s_ = 0.f, d_ = 0.f;
#pragma unroll
            for (int tn = 0; tn < 8; tn++) {
                const int c = wn * 64 + tn * 8 + 2 * tig;
                const float v0 = acc[tm][tn][rh * 2], v1 = acc[tm][tn][rh * 2 + 1];
                s_ = fmaf(v0, att_s[c], fmaf(v1, att_s[c + 1], s_));
                d_ = fmaf(v0, att_d[c], fmaf(v1, att_d[c + 1], d_));
                if (rok)
                    *(__half2*)(g_h + (size_t)r * FD + c) = __floats2half2_rn(v0, v1);
            }
            s_ += __shfl_xor_sync(0xffffffffu, s_, 1);
            s_ += __shfl_xor_sync(0xffffffffu, s_, 2);
            d_ += __shfl_xor_sync(0xffffffffu, d_, 1);
            d_ += __shfl_xor_sync(0xffffffffu, d_, 2);
            if (tig == 0 && rok) {
                g_asrc[r * HEADS + head] = s_;
                g_adst[r * HEADS + head] = d_;
            }
        }
    }
}

// ---------------- aggregation: TWO NODES per warp, interleaved ----------------
// Warp owns nodes 2w and 2w+1; main loop consumes 2 edges from EACH list per
// iteration -> 4 independent full-warp LDG.128 h-gathers in flight + two
// independent accumulation chains. Single pass, max-free softmax.
#define ACC8(aa, rr, ww) { \
    const __half2* _p = (const __half2*)&(rr); \
    const float2 _x0 = __half22float2(_p[0]), _x1 = __half22float2(_p[1]); \
    const float2 _x2 = __half22float2(_p[2]), _x3 = __half22float2(_p[3]); \
    aa[0] = fmaf((ww), _x0.x, aa[0]); aa[1] = fmaf((ww), _x0.y, aa[1]); \
    aa[2] = fmaf((ww), _x1.x, aa[2]); aa[3] = fmaf((ww), _x1.y, aa[3]); \
    aa[4] = fmaf((ww), _x2.x, aa[4]); aa[5] = fmaf((ww), _x2.y, aa[5]); \
    aa[6] = fmaf((ww), _x3.x, aa[6]); aa[7] = fmaf((ww), _x3.y, aa[7]); }

__global__ void __launch_bounds__(256) k_aggregate(
    const float* __restrict__ bias,
    float* __restrict__ outp)               // nullptr -> g_y
{
    const int gw = (blockIdx.x * blockDim.x + threadIdx.x) >> 5;
    const int lane = threadIdx.x & 31;
    const int n0 = gw * 2, n1 = gw * 2 + 1;
    if (n0 >= NN) return;
    const bool has1 = n1 < NN;
    const int hd = lane >> 3;

    const float ad0 = g_adst[n0 * HEADS + hd];
    const float ad1 = has1 ? g_adst[n1 * HEADS + hd] : 0.f;
    int k0 = g_off[n0];
    const int e0 = g_off[n0 + 1];
    int k1 = has1 ? g_off[n1] : 0;
    const int e1 = has1 ? g_off[n1 + 1] : 0;

    float a0[8], a1[8];
    float d0, d1 = 0.f;
    {   // self loop node0
        const float w = __expf(lrelu(g_asrc[n0 * HEADS + hd] + ad0));
        d0 = w;
        const uint4 raw = *(const uint4*)(g_h + (size_t)n0 * FD + lane * 8);
        const __half2* hp = (const __half2*)&raw;
        const float2 f0 = __half22float2(hp[0]), f1 = __half22float2(hp[1]);
        const float2 f2 = __half22float2(hp[2]), f3 = __half22float2(hp[3]);
        a0[0] = w * f0.x; a0[1] = w * f0.y; a0[2] = w * f1.x; a0[3] = w * f1.y;
        a0[4] = w * f2.x; a0[5] = w * f2.y; a0[6] = w * f3.x; a0[7] = w * f3.y;
    }
#pragma unroll
    for (int i = 0; i < 8; i++) a1[i] = 0.f;
    if (has1) {   // self loop node1
        const float w = __expf(lrelu(g_asrc[n1 * HEADS + hd] + ad1));
        d1 = w;
        const uint4 raw = *(const uint4*)(g_h + (size_t)n1 * FD + lane * 8);
        const __half2* hp = (const __half2*)&raw;
        const float2 f0 = __half22float2(hp[0]), f1 = __half22float2(hp[1]);
        const float2 f2 = __half22float2(hp[2]), f3 = __half22float2(hp[3]);
        a1[0] = w * f0.x; a1[1] = w * f0.y; a1[2] = w * f1.x; a1[3] = w * f1.y;
        a1[4] = w * f2.x; a1[5] = w * f2.y; a1[6] = w * f3.x; a1[7] = w * f3.y;
    }

    // interleaved main loop: 2 edges from each list per iteration
    while (k0 + 2 <= e0 && k1 + 2 <= e1) {
        const int sA = g_col[k0], sB = g_col[k0 + 1];
        const int sC = g_col[k1], sD = g_col[k1 + 1];
        const float eA = g_asrc[sA * HEADS + hd] + ad0;
        const float eB = g_asrc[sB * HEADS + hd] + ad0;
        const float eC = g_asrc[sC * HEADS + hd] + ad1;
        const float eD = g_asrc[sD * HEADS + hd] + ad1;
        const uint4 rA = *(const uint4*)(g_h + (size_t)sA * FD + lane * 8);
        const uint4 rB = *(const uint4*)(g_h + (size_t)sB * FD + lane * 8);
        const uint4 rC = *(const uint4*)(g_h + (size_t)sC * FD + lane * 8);
        const uint4 rD = *(const uint4*)(g_h + (size_t)sD * FD + lane * 8);
        const float wA = __expf(lrelu(eA)), wB = __expf(lrelu(eB));
        const float wC = __expf(lrelu(eC)), wD = __expf(lrelu(eD));
        d0 += wA + wB;
        d1 += wC + wD;
        ACC8(a0, rA, wA) ACC8(a0, rB, wB)
        ACC8(a1, rC, wC) ACC8(a1, rD, wD)
        k0 += 2; k1 += 2;
    }
    // tails (x2 unrolled where possible)
    for (; k0 + 2 <= e0; k0 += 2) {
        const int sA = g_col[k0], sB = g_col[k0 + 1];
        const float eA = g_asrc[sA * HEADS + hd] + ad0;
        const float eB = g_asrc[sB * HEADS + hd] + ad0;
        const uint4 rA = *(const uint4*)(g_h + (size_t)sA * FD + lane * 8);
        const uint4 rB = *(const uint4*)(g_h + (size_t)sB * FD + lane * 8);
        const float wA = __expf(lrelu(eA)), wB = __expf(lrelu(eB));
        d0 += wA + wB;
        ACC8(a0, rA, wA) ACC8(a0, rB, wB)
    }
    for (; k0 < e0; k0++) {
        const int s = g_col[k0];
        const float w = __expf(lrelu(g_asrc[s * HEADS + hd] + ad0));
        d0 += w;
        const uint4 raw = *(const uint4*)(g_h + (size_t)s * FD + lane * 8);
        ACC8(a0, raw, w)
    }
    for (; k1 + 2 <= e1; k1 += 2) {
        const int sC = g_col[k1], sD = g_col[k1 + 1];
        const float eC = g_asrc[sC * HEADS + hd] + ad1;
        const float eD = g_asrc[sD * HEADS + hd] + ad1;
        const uint4 rC = *(const uint4*)(g_h + (size_t)sC * FD + lane * 8);
        const uint4 rD = *(const uint4*)(g_h + (size_t)sD * FD + lane * 8);
        const float wC = __expf(lrelu(eC)), wD = __expf(lrelu(eD));
        d1 += wC + wD;
        ACC8(a1, rC, wC) ACC8(a1, rD, wD)
    }
    for (; k1 < e1; k1++) {
        const int s = g_col[k1];
        const float w = __expf(lrelu(g_asrc[s * HEADS + hd] + ad1));
        d1 += w;
        const uint4 raw = *(const uint4*)(g_h + (size_t)s * FD + lane * 8);
        ACC8(a1, raw, w)
    }

    // finalize both nodes: normalize, +bias, ELU, store
    float* outbase = outp ? outp : g_y;
    const float* bp = bias + lane * 8;
    {
        const float inv = 1.0f / (d0 + 1e-16f);
        float r[8];
#pragma unroll
        for (int i = 0; i < 8; i++) {
            r[i] = a0[i] * inv + bp[i];
            r[i] = r[i] > 0.f ? r[i] : expm1f(r[i]);
        }
        float* op = outbase + (size_t)n0 * FD + lane * 8;
        *(float4*)op       = make_float4(r[0], r[1], r[2], r[3]);
        *((float4*)op + 1) = make_float4(r[4], r[5], r[6], r[7]);
    }
    if (has1) {
        const float inv = 1.0f / (d1 + 1e-16f);
        float r[8];
#pragma unroll
        for (int i = 0; i < 8; i++) {
            r[i] = a1[i] * inv + bp[i];
            r[i] = r[i] > 0.f ? r[i] : expm1f(r[i]);
        }
        float* op = outbase + (size_t)n1 * FD + lane * 8;
        *(float4*)op       = make_float4(r[0], r[1], r[2], r[3]);
        *((float4*)op + 1) = make_float4(r[4], r[5], r[6], r[7]);
    }
}
#undef ACC8

// ---------------- launch ----------------
extern "C" void kernel_launch(void* const* d_in, const int* in_sizes, int n_in,
                              void* d_out, int out_size)
{
    const float* x   = (const float*)d_in[0];
    const int*   ei  = (const int*)d_in[1];
    const float* W1  = (const float*)d_in[2];
    const float* as1 = (const float*)d_in[3];
    const float* ad1 = (const float*)d_in[4];
    const float* b1  = (const float*)d_in[5];
    const float* W2  = (const float*)d_in[6];
    const float* as2 = (const float*)d_in[7];
    const float* ad2 = (const float*)d_in[8];
    const float* b2  = (const float*)d_in[9];

    const int* src = ei;            // edge_index row 0
    const int* dst = ei + NE;       // edge_index row 1

    const int ggrid = (NN + 63) / 64;
    const int nwarp = (NN + 1) / 2;                    // 2 nodes per warp
    const int agrid = (nwarp * 32 + 255) / 256;

    // order keeps k_gemm_att (layer 1) in the profiled 4th slot
    k_zero_cnt<<<(NN + 255) / 256, 256>>>();
    k_hist<<<(NE + 255) / 256, 256>>>(dst);
    k_scan<<<1, 1024>>>();                            // scan + re-zero g_cnt
    k_gemm_att<<<ggrid, 256>>>(x, W1, as1, ad1);      // <- profiled slot
    k_scatter<<<(NE + 255) / 256, 256>>>(src, dst);

    k_aggregate<<<agrid, 256>>>(b1, nullptr);
    k_gemm_att<<<ggrid, 256>>>(nullptr, W2, as2, ad2);
    k_aggregate<<<agrid, 256>>>(b2, (float*)d_out);
}

// round 11
// speedup vs baseline: 1.0809x; 1.0809x over previous
#include <cuda_runtime.h>
#include <cuda_fp16.h>
#include <math.h>

#define NN 50000
#define NE 800000
#define FD 256
#define HEADS 4
#define CH 64
#define GG 782              // gemm blocks: (NN+63)/64
#define HG 3125             // hist blocks: (NE+255)/256

// ---- scratch (static device globals: no runtime allocation) ----
__device__ __half g_h[(size_t)NN * FD];    // GEMM output (fp16 gather payload)
__device__ float  g_y[(size_t)NN * FD];    // layer-1 output (GEMM2 input)
__device__ float  g_asrc[NN * HEADS];
__device__ float  g_adst[NN * HEADS];
__device__ int    g_cnt[NN];               // static zero-init; scan re-zeros
__device__ int    g_off[NN + 1];
__device__ int    g_col[NE];               // CSR: src per position
__device__ int    g_pos[NE];               // per-edge intra-bucket position

__device__ __forceinline__ float lrelu(float x) { return fmaxf(x, 0.2f * x); }

__device__ __forceinline__ unsigned f2tf(float f) {
    unsigned u;
    asm("cvt.rna.tf32.f32 %0, %1;" : "=r"(u) : "f"(f));
    return u;
}

__device__ __forceinline__ void mma_tf32(float* c, const unsigned* a, const unsigned* b) {
    asm volatile(
        "mma.sync.aligned.m16n8k8.row.col.f32.tf32.tf32.f32 "
        "{%0,%1,%2,%3},{%4,%5,%6,%7},{%8,%9},{%0,%1,%2,%3};"
        : "+f"(c[0]), "+f"(c[1]), "+f"(c[2]), "+f"(c[3])
        : "r"(a[0]), "r"(a[1]), "r"(a[2]), "r"(a[3]), "r"(b[0]), "r"(b[1]));
}

// ---------------- fused GEMM + hist ----------------
// blocks [0,GG): R6 tf32 GEMM (block 64x256, 8 warps = 2wm x 4wn, warp 32x64,
//   fragment-major A, double-buffered smem, register prefetch, fused
//   attention-logit epilogue).
// blocks [GG, GG+nh): edge histogram (independent work, overlaps the GEMM).
__global__ void __launch_bounds__(256) k_gemm_att(
    const float* __restrict__ Ain,          // nullptr -> use g_y
    const float* __restrict__ W,
    const float* __restrict__ att_s,
    const float* __restrict__ att_d,
    const int* __restrict__ dstv)           // non-null: hist blocks appended
{
    if (blockIdx.x >= GG) {                 // -------- histogram branch -----
        const int e = (blockIdx.x - GG) * 256 + threadIdx.x;
        if (e < NE)
            g_pos[e] = atomicAdd(&g_cnt[dstv[e]], 1);
        return;
    }
    // ------------------------------- GEMM branch (R6 verbatim) ------------
    const float* A = Ain ? Ain : g_y;
    __shared__ unsigned sAf[2][1024];       // fragment-major A (4KB/stage)
    __shared__ unsigned sB[2][16][264];     // [k][n] stride 264 (conflict-free)

    const int t    = threadIdx.x;
    const int lane = t & 31;
    const int wid  = t >> 5;
    const int gid  = lane >> 2, tig = lane & 3;
    const int wm   = wid & 1,   wn  = wid >> 1;   // rows wm*32, cols wn*64
    const int row0 = blockIdx.x * 64;

    float acc[2][8][4] = {};

    const int ar = t >> 2, acb = (t & 3) * 4;     // A: row ar, cols acb..acb+3
    const int br = t >> 4, bc = (t & 15) * 4;     // B: row br, 4x 64-strided float4
    const bool arow_ok = (row0 + ar) < NN;
    const float* aptr = A + (size_t)(row0 + ar) * FD + acb;
    const float* bptr = W + (size_t)br * FD + bc;

    int a_st[4];
    {
        const int wm_s = ar >> 5, tm_s = (ar >> 4) & 1;
        const int rh_s = (ar >> 3) & 1, gid_s = ar & 7;
#pragma unroll
        for (int j = 0; j < 4; j++) {
            const int k = acb + j;
            const int kkb = k >> 3, tg = k & 3, kh = (k >> 2) & 1;
            a_st[j] = (kkb * 128 + wm_s * 64 + tm_s * 32 + gid_s * 4 + tg) * 4
                      + rh_s + 2 * kh;
        }
    }
    const int a_rd0 = (wm * 64 + gid * 4 + tig) * 4;
    const int b_rd  = tig * 264 + wn * 64 + gid;

    float4 aval = make_float4(0.f, 0.f, 0.f, 0.f);
    float4 bval[4];
    if (arow_ok) aval = *(const float4*)aptr;
#pragma unroll
    for (int sub = 0; sub < 4; sub++)
        bval[sub] = *(const float4*)(bptr + sub * 64);

    int st = 0;
    for (int k0 = 0; k0 < FD; k0 += 16) {
        sAf[st][a_st[0]] = f2tf(aval.x);
        sAf[st][a_st[1]] = f2tf(aval.y);
        sAf[st][a_st[2]] = f2tf(aval.z);
        sAf[st][a_st[3]] = f2tf(aval.w);
#pragma unroll
        for (int sub = 0; sub < 4; sub++)
            *(uint4*)&sB[st][br][bc + sub * 64] =
                make_uint4(f2tf(bval[sub].x), f2tf(bval[sub].y),
                           f2tf(bval[sub].z), f2tf(bval[sub].w));
        __syncthreads();

        if (k0 + 16 < FD) {                  // prefetch next chunk into regs
            aval = make_float4(0.f, 0.f, 0.f, 0.f);
            if (arow_ok) aval = *(const float4*)(aptr + k0 + 16);
#pragma unroll
            for (int sub = 0; sub < 4; sub++)
                bval[sub] = *(const float4*)(bptr + (size_t)(k0 + 16) * FD + sub * 64);
        }

        const unsigned* sa = sAf[st];
        const unsigned* sb = &sB[st][0][0] + b_rd;
#pragma unroll
        for (int kkb = 0; kkb < 2; kkb++) {
            uint4 af0 = *(const uint4*)(sa + kkb * 512 + a_rd0);        // tm=0
            uint4 af1 = *(const uint4*)(sa + kkb * 512 + a_rd0 + 128);  // tm=1
            const unsigned* b0 = sb + kkb * (8 * 264);
            unsigned bf[8][2];
#pragma unroll
            for (int tn = 0; tn < 8; tn++) {
                bf[tn][0] = b0[tn * 8];
                bf[tn][1] = b0[4 * 264 + tn * 8];
            }
#pragma unroll
            for (int tn = 0; tn < 8; tn++) {
                mma_tf32(acc[0][tn], (const unsigned*)&af0, bf[tn]);
                mma_tf32(acc[1][tn], (const unsigned*)&af1, bf[tn]);
            }
        }
        st ^= 1;
    }

    // ---- epilogue: store h (fp16), fused per-head attention dots ----
    const int head = wn;
#pragma unroll
    for (int tm = 0; tm < 2; tm++) {
#pragma unroll
        for (int rh = 0; rh < 2; rh++) {
            const int r = row0 + wm * 32 + tm * 16 + rh * 8 + gid;
            const bool rok = r < NN;
            float s_ = 0.f, d_ = 0.f;
#pragma unroll
            for (int tn = 0; tn < 8; tn++) {
                const int c = wn * 64 + tn * 8 + 2 * tig;
                const float v0 = acc[tm][tn][rh * 2], v1 = acc[tm][tn][rh * 2 + 1];
                s_ = fmaf(v0, att_s[c], fmaf(v1, att_s[c + 1], s_));
                d_ = fmaf(v0, att_d[c], fmaf(v1, att_d[c + 1], d_));
                if (rok)
                    *(__half2*)(g_h + (size_t)r * FD + c) = __floats2half2_rn(v0, v1);
            }
            s_ += __shfl_xor_sync(0xffffffffu, s_, 1);
            s_ += __shfl_xor_sync(0xffffffffu, s_, 2);
            d_ += __shfl_xor_sync(0xffffffffu, d_, 1);
            d_ += __shfl_xor_sync(0xffffffffu, d_, 2);
            if (tig == 0 && rok) {
                g_asrc[r * HEADS + head] = s_;
                g_adst[r * HEADS + head] = d_;
            }
        }
    }
}

// ---------------- scan: exclusive prefix of g_cnt -> g_off, re-zero g_cnt ----
__global__ void k_scan() {
    const int T = 1024, PER = (NN + T - 1) / T;   // 49
    __shared__ int wsum[32];
    const int t = threadIdx.x, lane = t & 31, wid = t >> 5;
    const int base = t * PER;

    int sum = 0;
    for (int i = 0; i < PER; i++) {
        int idx = base + i;
        if (idx < NN) sum += g_cnt[idx];
    }
    int v = sum;
#pragma unroll
    for (int o = 1; o < 32; o <<= 1) {
        int n = __shfl_up_sync(0xffffffffu, v, o);
        if (lane >= o) v += n;
    }
    if (lane == 31) wsum[wid] = v;
    __syncthreads();
    if (wid == 0) {
        int wv = wsum[lane];
#pragma unroll
        for (int o = 1; o < 32; o <<= 1) {
            int n = __shfl_up_sync(0xffffffffu, wv, o);
            if (lane >= o) wv += n;
        }
        wsum[lane] = wv;
    }
    __syncthreads();
    int run = v - sum + (wid > 0 ? wsum[wid - 1] : 0);
    for (int i = 0; i < PER; i++) {
        int idx = base + i;
        if (idx < NN) {
            int c = g_cnt[idx];
            g_off[idx] = run;
            run += c;
            g_cnt[idx] = 0;                  // reset for next call's hist
        }
    }
    if (t == 0) g_off[NN] = wsum[31];
}

// ---------------- atomic-free scatter (uses positions recorded by hist) ----
__global__ void k_scatter(const int* __restrict__ src, const int* __restrict__ dst) {
    int e = blockIdx.x * blockDim.x + threadIdx.x;
    if (e < NE)
        g_col[g_off[dst[e]] + g_pos[e]] = src[e];
}

// ---------------- per-dst-node aggregation (R6 verbatim) ----------------
// One warp per node; single pass, max-free softmax; fp16 h rows
// (1 LDG.128/lane/edge) + x4 batched unroll.
__global__ void __launch_bounds__(256) k_aggregate(
    const float* __restrict__ bias,
    float* __restrict__ outp)               // nullptr -> g_y
{
    const int w = (blockIdx.x * blockDim.x + threadIdx.x) >> 5;
    const int lane = threadIdx.x & 31;
    if (w >= NN) return;
    const int hd = lane >> 3;
    const float ad = g_adst[w * HEADS + hd];
    const int beg = g_off[w], end = g_off[w + 1];

    float wt = __expf(lrelu(g_asrc[w * HEADS + hd] + ad));   // self loop
    float denom = wt;
    float a0, a1, a2, a3, a4, a5, a6, a7;
    {
        const uint4 raw = *(const uint4*)(g_h + (size_t)w * FD + lane * 8);
        const __half2* hp = (const __half2*)&raw;
        const float2 f0 = __half22float2(hp[0]), f1 = __half22float2(hp[1]);
        const float2 f2 = __half22float2(hp[2]), f3 = __half22float2(hp[3]);
        a0 = wt * f0.x; a1 = wt * f0.y; a2 = wt * f1.x; a3 = wt * f1.y;
        a4 = wt * f2.x; a5 = wt * f2.y; a6 = wt * f3.x; a7 = wt * f3.y;
    }

    int k = beg;
    for (; k + 4 <= end; k += 4) {
        const int s0 = g_col[k], s1 = g_col[k + 1];
        const int s2 = g_col[k + 2], s3 = g_col[k + 3];
        const float e0 = g_asrc[s0 * HEADS + hd] + ad;
        const float e1 = g_asrc[s1 * HEADS + hd] + ad;
        const float e2 = g_asrc[s2 * HEADS + hd] + ad;
        const float e3 = g_asrc[s3 * HEADS + hd] + ad;
        const uint4 r0 = *(const uint4*)(g_h + (size_t)s0 * FD + lane * 8);
        const uint4 r1 = *(const uint4*)(g_h + (size_t)s1 * FD + lane * 8);
        const uint4 r2 = *(const uint4*)(g_h + (size_t)s2 * FD + lane * 8);
        const uint4 r3 = *(const uint4*)(g_h + (size_t)s3 * FD + lane * 8);
        const float w0 = __expf(lrelu(e0)), w1 = __expf(lrelu(e1));
        const float w2 = __expf(lrelu(e2)), w3 = __expf(lrelu(e3));
        denom += (w0 + w1) + (w2 + w3);
        const __half2* p0 = (const __half2*)&r0;
        const __half2* p1 = (const __half2*)&r1;
        const __half2* p2 = (const __half2*)&r2;
        const __half2* p3 = (const __half2*)&r3;
#define ACC8(pp, ww) { \
        const float2 x0 = __half22float2((pp)[0]), x1 = __half22float2((pp)[1]); \
        const float2 x2 = __half22float2((pp)[2]), x3 = __half22float2((pp)[3]); \
        a0 = fmaf((ww), x0.x, a0); a1 = fmaf((ww), x0.y, a1); \
        a2 = fmaf((ww), x1.x, a2); a3 = fmaf((ww), x1.y, a3); \
        a4 = fmaf((ww), x2.x, a4); a5 = fmaf((ww), x2.y, a5); \
        a6 = fmaf((ww), x3.x, a6); a7 = fmaf((ww), x3.y, a7); }
        ACC8(p0, w0) ACC8(p1, w1) ACC8(p2, w2) ACC8(p3, w3)
    }
    for (; k < end; k++) {
        const int s = g_col[k];
        const float wt1 = __expf(lrelu(g_asrc[s * HEADS + hd] + ad));
        denom += wt1;
        const uint4 raw = *(const uint4*)(g_h + (size_t)s * FD + lane * 8);
        const __half2* hp = (const __half2*)&raw;
        ACC8(hp, wt1)
    }
#undef ACC8

    const float inv = 1.0f / (denom + 1e-16f);
    const float* bp = bias + lane * 8;
    float r0 = a0 * inv + bp[0], r1 = a1 * inv + bp[1];
    float r2 = a2 * inv + bp[2], r3 = a3 * inv + bp[3];
    float r4 = a4 * inv + bp[4], r5 = a5 * inv + bp[5];
    float r6 = a6 * inv + bp[6], r7 = a7 * inv + bp[7];
    r0 = r0 > 0.f ? r0 : expm1f(r0);  r1 = r1 > 0.f ? r1 : expm1f(r1);
    r2 = r2 > 0.f ? r2 : expm1f(r2);  r3 = r3 > 0.f ? r3 : expm1f(r3);
    r4 = r4 > 0.f ? r4 : expm1f(r4);  r5 = r5 > 0.f ? r5 : expm1f(r5);
    r6 = r6 > 0.f ? r6 : expm1f(r6);  r7 = r7 > 0.f ? r7 : expm1f(r7);

    float* op = (outp ? outp : g_y) + (size_t)w * FD + lane * 8;
    *(float4*)op       = make_float4(r0, r1, r2, r3);
    *((float4*)op + 1) = make_float4(r4, r5, r6, r7);
}

// ---------------- launch ----------------
extern "C" void kernel_launch(void* const* d_in, const int* in_sizes, int n_in,
                              void* d_out, int out_size)
{
    const float* x   = (const float*)d_in[0];
    const int*   ei  = (const int*)d_in[1];
    const float* W1  = (const float*)d_in[2];
    const float* as1 = (const float*)d_in[3];
    const float* ad1 = (const float*)d_in[4];
    const float* b1  = (const float*)d_in[5];
    const float* W2  = (const float*)d_in[6];
    const float* as2 = (const float*)d_in[7];
    const float* ad2 = (const float*)d_in[8];
    const float* b2  = (const float*)d_in[9];

    const int* src = ei;            // edge_index row 0
    const int* dst = ei + NE;       // edge_index row 1

    const int agrid = (NN * 32 + 255) / 256;

    // 6 launches; slot 4 (profiled) = k_aggregate (first agg profile!)
    k_gemm_att<<<GG + HG, 256>>>(x, W1, as1, ad1, dst);   // gemm1 || hist
    k_scan<<<1, 1024>>>();                                // prefix + re-zero
    k_scatter<<<(NE + 255) / 256, 256>>>(src, dst);       // atomic-free
    k_aggregate<<<agrid, 256>>>(b1, nullptr);             // <- profiled slot
    k_gemm_att<<<GG, 256>>>(nullptr, W2, as2, ad2, nullptr);
    k_aggregate<<<agrid, 256>>>(b2, (float*)d_out);
}